// round 14
// baseline (speedup 1.0000x reference)
#include <cuda_runtime.h>
#include <cuda_bf16.h>
#include <cstdint>

// Problem constants
#define M_ROWS   4096          // b*NT*2*NO = 16*8*32
#define K_VIS    2048
#define FEAT     512
#define BT       128           // b*NT
#define NO       16
#define TGT      24
#define N_EDGE   (BT * NO * NO)        // 32768
#define OUT_LOGITS (N_EDGE * TGT)      // 786432

typedef unsigned long long ull;

// Scratch (device globals; referenced ONLY in device code)
// NOTE: g_Ws/g_Wo/g_W2s/g_W2o are stored TRANSPOSED: [TGT][FEAT]
__device__ __align__(16) float g_h1[M_ROWS * FEAT];
__device__ __align__(16) float g_Ws[TGT * FEAT];     // (wf @ wr_top)^T
__device__ __align__(16) float g_Wo[TGT * FEAT];     // (wf @ wr_bot)^T
__device__ __align__(16) float g_W2s[TGT * FEAT];    // (w2 @ Ws)^T
__device__ __align__(16) float g_W2o[TGT * FEAT];    // (w2 @ Wo)^T
__device__ float g_bs[TGT];            // bf @ wr_top
__device__ float g_bo[TGT];            // bf @ wr_bot + br
__device__ float g_bs2[TGT];           // b2 @ Ws + bs
__device__ float g_bo2[TGT];           // b2 @ Wo + bo
__device__ __align__(16) float g_sout[BT * NO * TGT];
__device__ __align__(16) float g_oout[BT * NO * TGT];
__device__ float g_p1[128];
__device__ float g_p2[128];
__device__ int   g_tgt_is64;

// ---------------------------------------------------------------------------
// PTX helpers
// ---------------------------------------------------------------------------
__device__ __forceinline__ unsigned su32(const void* p) {
    return (unsigned)__cvta_generic_to_shared(p);
}
__device__ __forceinline__ unsigned packbf(float f0, float f1) {
    unsigned r;
    asm("cvt.rn.bf16x2.f32 %0, %1, %2;" : "=r"(r) : "f"(f1), "f"(f0));
    return r;
}
__device__ __forceinline__ void ldsm_x4(unsigned& r0, unsigned& r1,
                                        unsigned& r2, unsigned& r3,
                                        unsigned addr) {
    asm volatile("ldmatrix.sync.aligned.m8n8.x4.shared.b16 {%0,%1,%2,%3}, [%4];"
                 : "=r"(r0), "=r"(r1), "=r"(r2), "=r"(r3) : "r"(addr));
}
__device__ __forceinline__ void ldsm_x4t(unsigned& r0, unsigned& r1,
                                         unsigned& r2, unsigned& r3,
                                         unsigned addr) {
    asm volatile("ldmatrix.sync.aligned.m8n8.x4.trans.shared.b16 {%0,%1,%2,%3}, [%4];"
                 : "=r"(r0), "=r"(r1), "=r"(r2), "=r"(r3) : "r"(addr));
}
__device__ __forceinline__ void mma16816(float* c, const unsigned* a,
                                         const unsigned* b) {
    asm volatile(
        "mma.sync.aligned.m16n8k16.row.col.f32.bf16.bf16.f32 "
        "{%0,%1,%2,%3},{%4,%5,%6,%7},{%8,%9},{%0,%1,%2,%3};"
        : "+f"(c[0]), "+f"(c[1]), "+f"(c[2]), "+f"(c[3])
        : "r"(a[0]), "r"(a[1]), "r"(a[2]), "r"(a[3]), "r"(b[0]), "r"(b[1]));
}
__device__ __forceinline__ void split_store(float4 v, void* hp, void* lp) {
    unsigned h01 = packbf(v.x, v.y);
    unsigned h23 = packbf(v.z, v.w);
    float h0 = __uint_as_float(h01 << 16);
    float h1 = __uint_as_float(h01 & 0xffff0000u);
    float h2 = __uint_as_float(h23 << 16);
    float h3 = __uint_as_float(h23 & 0xffff0000u);
    unsigned l01 = packbf(v.x - h0, v.y - h1);
    unsigned l23 = packbf(v.z - h2, v.w - h3);
    *reinterpret_cast<uint2*>(hp) = make_uint2(h01, h23);
    *reinterpret_cast<uint2*>(lp) = make_uint2(l01, l23);
}
__device__ __forceinline__ void ffma2(ull& d, ull a, ull b) {
    asm("fma.rn.f32x2 %0, %1, %2, %0;" : "+l"(d) : "l"(a), "l"(b));
}
__device__ __forceinline__ void unpack2(float& lo, float& hi, ull v) {
    asm("mov.b64 {%0, %1}, %2;" : "=f"(lo), "=f"(hi) : "l"(v));
}

// ---------------------------------------------------------------------------
// GEMM1 via tensor cores (bf16 split, fp32-accurate) — proven, unchanged.
// g_h1 = relu(src @ w1 + b1),  M=4096, N=512, K=2048.
// ---------------------------------------------------------------------------
#define BM 128
#define BN 128
#define CK 32
#define APAD 40
#define BPAD 136

__global__ __launch_bounds__(256) void mma_gemm_relu(
    const float* __restrict__ A, const float* __restrict__ B,
    const float* __restrict__ bias)
{
    __shared__ __align__(16) __nv_bfloat16 sAh[BM][APAD];
    __shared__ __align__(16) __nv_bfloat16 sAl[BM][APAD];
    __shared__ __align__(16) __nv_bfloat16 sBh[CK][BPAD];
    __shared__ __align__(16) __nv_bfloat16 sBl[CK][BPAD];

    const int tid = threadIdx.x;
    const int lane = tid & 31;
    const int wid = tid >> 5;
    const int wm = wid & 1;
    const int wn = wid >> 1;
    const int bm = blockIdx.y * BM;
    const int bn = blockIdx.x * BN;

    const int arow = tid >> 3;
    const int acol = (tid & 7) * 4;
    const int brow = tid >> 5;
    const int bcol = (tid & 31) * 4;

    const float* Ap = A + (size_t)(bm + arow) * K_VIS + acol;
    const float* Bp = B + (size_t)brow * FEAT + bn + bcol;

    unsigned aAddrH[4], aAddrL[4];
#pragma unroll
    for (int mi = 0; mi < 4; mi++) {
        const int r = wm * 64 + mi * 16 + (lane & 15);
        const int c = (lane >> 4) * 8;
        aAddrH[mi] = su32(&sAh[r][c]);
        aAddrL[mi] = su32(&sAl[r][c]);
    }
    unsigned bAddrH[2], bAddrL[2];
#pragma unroll
    for (int nh = 0; nh < 2; nh++) {
        const int r = (lane & 15);
        const int c = wn * 32 + nh * 16 + (lane >> 4) * 8;
        bAddrH[nh] = su32(&sBh[r][c]);
        bAddrL[nh] = su32(&sBl[r][c]);
    }

    float acc[4][4][4];
#pragma unroll
    for (int mi = 0; mi < 4; mi++)
#pragma unroll
        for (int ni = 0; ni < 4; ni++)
#pragma unroll
            for (int q = 0; q < 4; q++) acc[mi][ni][q] = 0.0f;

    float4 aS[4], bS[4];
#pragma unroll
    for (int j = 0; j < 4; j++) {
        aS[j] = *reinterpret_cast<const float4*>(Ap + (size_t)j * 32 * K_VIS);
        bS[j] = *reinterpret_cast<const float4*>(Bp + (size_t)j * 8 * FEAT);
    }
#pragma unroll
    for (int j = 0; j < 4; j++) {
        split_store(aS[j], &sAh[arow + j * 32][acol], &sAl[arow + j * 32][acol]);
        split_store(bS[j], &sBh[brow + j * 8][bcol], &sBl[brow + j * 8][bcol]);
    }
    __syncthreads();

    const int nCh = K_VIS / CK;    // 64
    for (int ch = 0; ch < nCh; ch++) {
        const bool more = (ch + 1 < nCh);
        if (more) {
            const float* Ap2 = Ap + (ch + 1) * CK;
            const float* Bp2 = Bp + (size_t)(ch + 1) * CK * FEAT;
#pragma unroll
            for (int j = 0; j < 4; j++) {
                aS[j] = *reinterpret_cast<const float4*>(Ap2 + (size_t)j * 32 * K_VIS);
                bS[j] = *reinterpret_cast<const float4*>(Bp2 + (size_t)j * 8 * FEAT);
            }
        }

#pragma unroll
        for (int ks = 0; ks < 2; ks++) {
            const unsigned koff = ks * 16 * 2;
            unsigned ah[4][4], al[4][4], bh[2][4], bl[2][4];
#pragma unroll
            for (int mi = 0; mi < 4; mi++) {
                ldsm_x4(ah[mi][0], ah[mi][1], ah[mi][2], ah[mi][3],
                        aAddrH[mi] + koff);
                ldsm_x4(al[mi][0], al[mi][1], al[mi][2], al[mi][3],
                        aAddrL[mi] + koff);
            }
            const unsigned krow = ks * 16 * (BPAD * 2);
#pragma unroll
            for (int nh = 0; nh < 2; nh++) {
                ldsm_x4t(bh[nh][0], bh[nh][1], bh[nh][2], bh[nh][3],
                         bAddrH[nh] + krow);
                ldsm_x4t(bl[nh][0], bl[nh][1], bl[nh][2], bl[nh][3],
                         bAddrL[nh] + krow);
            }
#pragma unroll
            for (int mi = 0; mi < 4; mi++)
#pragma unroll
                for (int ni = 0; ni < 4; ni++) {
                    const int nh = ni >> 1;
                    const int sel = (ni & 1) * 2;
                    mma16816(acc[mi][ni], ah[mi], &bh[nh][sel]);
                    mma16816(acc[mi][ni], ah[mi], &bl[nh][sel]);
                    mma16816(acc[mi][ni], al[mi], &bh[nh][sel]);
                }
        }

        // Barrier 1: all warps done reading smem (ldsm) before overwrite
        __syncthreads();
        if (more) {
#pragma unroll
            for (int j = 0; j < 4; j++) {
                split_store(aS[j], &sAh[arow + j * 32][acol],
                            &sAl[arow + j * 32][acol]);
                split_store(bS[j], &sBh[brow + j * 8][bcol],
                            &sBl[brow + j * 8][bcol]);
            }
            // Barrier 2: stores visible before next chunk's ldsm
            __syncthreads();
        }
    }

#pragma unroll
    for (int ni = 0; ni < 4; ni++) {
        const int cn = bn + wn * 32 + ni * 8 + (lane & 3) * 2;
        const float2 bv = *reinterpret_cast<const float2*>(&bias[cn]);
#pragma unroll
        for (int mi = 0; mi < 4; mi++) {
            const int r0 = bm + wm * 64 + mi * 16 + (lane >> 2);
            float2 v0, v1;
            v0.x = fmaxf(acc[mi][ni][0] + bv.x, 0.0f);
            v0.y = fmaxf(acc[mi][ni][1] + bv.y, 0.0f);
            v1.x = fmaxf(acc[mi][ni][2] + bv.x, 0.0f);
            v1.y = fmaxf(acc[mi][ni][3] + bv.y, 0.0f);
            *reinterpret_cast<float2*>(&g_h1[(size_t)r0 * FEAT + cn]) = v0;
            *reinterpret_cast<float2*>(&g_h1[(size_t)(r0 + 8) * FEAT + cn]) = v1;
        }
    }
}

// ---------------------------------------------------------------------------
// proj4g: warp computes acc[t] = sum over 128 f' (chunk kc) of arow[f']*WT[t][f']
// WT is TRANSPOSED [TGT][FEAT] -> every load is a warp-coalesced float4.
// (used by precompute kernels; unchanged from R13)
// ---------------------------------------------------------------------------
__device__ __forceinline__ void proj4g(
    const float* __restrict__ arow, const float* __restrict__ WT,
    int kc, int lane, float* acc)
{
    const int off = kc * 128 + lane * 4;
    const float4 v = *reinterpret_cast<const float4*>(arow + off);
#pragma unroll
    for (int t = 0; t < TGT; t++) {
        const float4 p =
            *reinterpret_cast<const float4*>(WT + (size_t)t * FEAT + off);
        float s = v.x * p.x;
        s = fmaf(v.y, p.y, s);
        s = fmaf(v.z, p.z, s);
        s = fmaf(v.w, p.w, s);
        acc[t] = s;
    }
#pragma unroll
    for (int t = 0; t < TGT; t++)
#pragma unroll
        for (int o = 16; o > 0; o >>= 1)
            acc[t] += __shfl_xor_sync(0xFFFFFFFFu, acc[t], o);
}

// ---------------------------------------------------------------------------
// Fused precompute A (unchanged from R13)
// ---------------------------------------------------------------------------
__global__ __launch_bounds__(256) void pre_kernel_A(
    const float* __restrict__ wf, const float* __restrict__ wr,
    const float* __restrict__ bf, const float* __restrict__ br,
    const int* __restrict__ tgt32)
{
    __shared__ float sbuf[TGT * FEAT];   // 48KB exactly; reused as sp later
    const int gx = blockIdx.x;
    const int w = threadIdx.x >> 5;
    const int lane = threadIdx.x & 31;

    if (gx < 512) {
        const int half = gx >> 8;
        const float* wrh = wr + (size_t)half * FEAT * TGT;
        for (int i4 = threadIdx.x; i4 < FEAT * TGT / 4; i4 += 256) {
            const float4 vv =
                *reinterpret_cast<const float4*>(wrh + (size_t)i4 * 4);
            const int e0 = i4 * 4;
            sbuf[(e0 % TGT) * FEAT + (e0 / TGT)] = vv.x;
            sbuf[((e0 + 1) % TGT) * FEAT + ((e0 + 1) / TGT)] = vv.y;
            sbuf[((e0 + 2) % TGT) * FEAT + ((e0 + 2) / TGT)] = vv.z;
            sbuf[((e0 + 3) % TGT) * FEAT + ((e0 + 3) / TGT)] = vv.w;
        }
        __syncthreads();

        const int f = (gx & 255) * 2 + (w >> 2);
        const int kc = w & 3;
        float acc[TGT];
        proj4g(wf + (size_t)f * FEAT, sbuf, kc, lane, acc);

        __syncthreads();
        if (lane < TGT) sbuf[w * TGT + lane] = acc[lane];
        __syncthreads();
        if ((w & 3) == 0 && lane < TGT) {
            const float s = sbuf[w * TGT + lane] + sbuf[(w + 1) * TGT + lane]
                          + sbuf[(w + 2) * TGT + lane]
                          + sbuf[(w + 3) * TGT + lane];
            float* dst = half ? g_Wo : g_Ws;
            dst[(size_t)lane * FEAT + f] = s;
        }
    } else if (gx < 514) {
        const int half = gx - 512;
#pragma unroll
        for (int rep = 0; rep < 3; rep++) {
            const int t = w + rep * 8;
            float s = 0.0f;
#pragma unroll
            for (int i = 0; i < 16; i++) {
                const int f = lane + 32 * i;
                s = fmaf(bf[f], wr[(size_t)(half * FEAT + f) * TGT + t], s);
            }
#pragma unroll
            for (int o = 16; o > 0; o >>= 1)
                s += __shfl_xor_sync(0xFFFFFFFFu, s, o);
            if (lane == 0) {
                if (half == 0) g_bs[t] = s;
                else           g_bo[t] = s + br[t];
            }
        }
    } else {
        if (threadIdx.x == 0) {
            int allzero = 1;
            for (int i = 1; i < 128; i += 2)
                if (tgt32[i] != 0) { allzero = 0; break; }
            g_tgt_is64 = allzero;
        }
    }
}

// ---------------------------------------------------------------------------
// Fused precompute B (unchanged from R13)
// ---------------------------------------------------------------------------
__global__ __launch_bounds__(256) void pre_kernel_B(
    const float* __restrict__ w2, const float* __restrict__ b2)
{
    __shared__ float sp[8 * TGT];
    const int gx = blockIdx.x;
    const int w = threadIdx.x >> 5;
    const int lane = threadIdx.x & 31;

    if (gx < 512) {
        const int half = gx >> 8;
        const float* P = half ? g_Wo : g_Ws;      // [TGT][FEAT]
        float* dst = half ? g_W2o : g_W2s;        // [TGT][FEAT]
        const int f = (gx & 255) * 2 + (w >> 2);
        const int kc = w & 3;

        float acc[TGT];
        proj4g(w2 + (size_t)f * FEAT, P, kc, lane, acc);

        if (lane < TGT) sp[w * TGT + lane] = acc[lane];
        __syncthreads();
        if ((w & 3) == 0 && lane < TGT) {
            const float s = sp[w * TGT + lane] + sp[(w + 1) * TGT + lane]
                          + sp[(w + 2) * TGT + lane]
                          + sp[(w + 3) * TGT + lane];
            dst[(size_t)lane * FEAT + f] = s;
        }
    } else if (gx < 514) {
        const int half = gx - 512;
        const float* W = half ? g_Wo : g_Ws;      // [TGT][FEAT]
#pragma unroll
        for (int rep = 0; rep < 3; rep++) {
            const int t = w + rep * 8;
            float s = 0.0f;
#pragma unroll
            for (int i = 0; i < 16; i++) {
                const int f = lane + 32 * i;
                s = fmaf(b2[f], W[(size_t)t * FEAT + f], s);
            }
#pragma unroll
            for (int o = 16; o > 0; o >>= 1)
                s += __shfl_xor_sync(0xFFFFFFFFu, s, o);
            if (lane == 0) {
                if (half == 0) g_bs2[t] = s + g_bs[t];
                else           g_bo2[t] = s + g_bo[t];
            }
        }
    }
}

// ---------------------------------------------------------------------------
// Rel projection v3: lane = row. 64 blocks x 256 threads.
// Block covers 64 rows (2 frames). Warp w: type tw = w&1, k-chunk kc = w>>1.
// Lane's row: frame = lane>>4, n = lane&15 -> row = base + frame*32 + tw*16 + n.
// Weight loads WT[t][k..k+3] are warp-uniform (1 L1 line, read once per warp).
// f32x2 accumulators pack {even-k, odd-k} partial sums.
// ---------------------------------------------------------------------------
__global__ __launch_bounds__(256) void rel_small_kernel()
{
    __shared__ float sh[8][32][TGT];   // 24 KB partials
    const int w = threadIdx.x >> 5;
    const int lane = threadIdx.x & 31;
    const int tw = w & 1;              // 0 = subject, 1 = object
    const int kc = w >> 1;             // 0..3 (128-k chunk)
    const int rbase = blockIdx.x * 64;
    const int row = rbase + ((lane >> 4) << 5) + tw * NO + (lane & 15);

    const float* __restrict__ WT = tw ? g_W2o : g_W2s;   // [TGT][FEAT]
    const float* __restrict__ hrow = g_h1 + (size_t)row * FEAT + kc * 128;
    const float* __restrict__ wbase = WT + kc * 128;

    ull accp[TGT];
#pragma unroll
    for (int t = 0; t < TGT; t++) accp[t] = 0ull;

#pragma unroll 4
    for (int kg = 0; kg < 32; kg++) {
        const float4 v4 = *reinterpret_cast<const float4*>(hrow + kg * 4);
        const ull v01 = reinterpret_cast<const ull*>(&v4)[0];
        const ull v23 = reinterpret_cast<const ull*>(&v4)[1];
#pragma unroll
        for (int t = 0; t < TGT; t++) {
            const float4 w4 = __ldg(reinterpret_cast<const float4*>(
                wbase + (size_t)t * FEAT + kg * 4));
            const ull w01 = reinterpret_cast<const ull*>(&w4)[0];
            const ull w23 = reinterpret_cast<const ull*>(&w4)[1];
            ffma2(accp[t], v01, w01);
            ffma2(accp[t], v23, w23);
        }
    }

    // unpack pairs -> scalar partial, stash in smem
#pragma unroll
    for (int t = 0; t < TGT; t++) {
        float lo, hi;
        unpack2(lo, hi, accp[t]);
        sh[w][lane][t] = lo + hi;
    }
    __syncthreads();

    // Epilogue: 64 rows x 24 t = 1536 outputs, 6 per thread
#pragma unroll
    for (int q = 0; q < 6; q++) {
        const int idx = threadIdx.x * 6 + q;
        const int rl = idx / TGT;          // 0..63 local row
        const int t = idx - rl * TGT;
        const int frame = rl >> 5;
        const int within = rl & 31;
        const int type = within >> 4;
        const int n = within & 15;
        const int lsrc = (frame << 4) + n;
        float v = sh[0 * 2 + type][lsrc][t] + sh[1 * 2 + type][lsrc][t]
                + sh[2 * 2 + type][lsrc][t] + sh[3 * 2 + type][lsrc][t];
        v += type ? g_bo2[t] : g_bs2[t];
        const int bt = blockIdx.x * 2 + frame;
        float* dst = type ? g_oout : g_sout;
        dst[(size_t)(bt * NO + n) * TGT + t] = v;
    }
}

// ---------------------------------------------------------------------------
// Fused edge combine + weighted-NLL partials (unchanged).
// ---------------------------------------------------------------------------
__global__ __launch_bounds__(256) void combine_loss_kernel(
    const int* __restrict__ tgt32, float* __restrict__ out,
    float* __restrict__ tgtf)
{
    __shared__ float ss[NO * TGT];
    __shared__ float so[NO * TGT];
    __shared__ float sh1[256], sh2[256];

    const int bt = blockIdx.x;
    if (threadIdx.x < 96) {
        const int o = threadIdx.x * 4;
        *reinterpret_cast<float4*>(&ss[o]) =
            *reinterpret_cast<const float4*>(&g_sout[(size_t)bt * NO * TGT + o]);
        *reinterpret_cast<float4*>(&so[o]) =
            *reinterpret_cast<const float4*>(&g_oout[(size_t)bt * NO * TGT + o]);
    }
    __syncthreads();

    const int e = threadIdx.x;
    const int i = e >> 4;
    const int j = e & 15;
    const int r = bt * 256 + e;

    float lg[TGT];
#pragma unroll
    for (int t = 0; t < TGT; t++) lg[t] = ss[i * TGT + t] + so[j * TGT + t];

    float* op = out + (size_t)r * TGT;
#pragma unroll
    for (int q = 0; q < 6; q++)
        *reinterpret_cast<float4*>(op + q * 4) =
            make_float4(lg[q * 4], lg[q * 4 + 1], lg[q * 4 + 2], lg[q * 4 + 3]);

    float m = lg[0];
#pragma unroll
    for (int t = 1; t < TGT; t++) m = fmaxf(m, lg[t]);
    float s = 0.0f;
#pragma unroll
    for (int t = 0; t < TGT; t++) s += expf(lg[t] - m);
    const int tg = g_tgt_is64 ? tgt32[2 * r] : tgt32[r];
    const float nll = logf(s) + m - lg[tg];
    const float wgt = (tg == 0) ? 1.0f : 100.0f;
    tgtf[r] = (float)tg;

    sh1[e] = wgt * nll;
    sh2[e] = wgt;
    __syncthreads();
    for (int off = 128; off > 0; off >>= 1) {
        if (e < off) {
            sh1[e] += sh1[e + off];
            sh2[e] += sh2[e + off];
        }
        __syncthreads();
    }
    if (e == 0) { g_p1[bt] = sh1[0]; g_p2[bt] = sh2[0]; }
}

__global__ __launch_bounds__(128) void loss_final_kernel(float* __restrict__ loss)
{
    __shared__ float sh1[128], sh2[128];
    sh1[threadIdx.x] = g_p1[threadIdx.x];
    sh2[threadIdx.x] = g_p2[threadIdx.x];
    __syncthreads();
    for (int off = 64; off > 0; off >>= 1) {
        if (threadIdx.x < off) {
            sh1[threadIdx.x] += sh1[threadIdx.x + off];
            sh2[threadIdx.x] += sh2[threadIdx.x + off];
        }
        __syncthreads();
    }
    if (threadIdx.x == 0) loss[0] = sh1[0] / sh2[0];
}

// ---------------------------------------------------------------------------
extern "C" void kernel_launch(void* const* d_in, const int* in_sizes, int n_in,
                              void* d_out, int out_size)
{
    const float* src   = (const float*)d_in[0];
    const int*   tgt32 = (const int*)d_in[1];
    const float* w1 = (const float*)d_in[2];
    const float* b1 = (const float*)d_in[3];
    const float* w2 = (const float*)d_in[4];
    const float* b2 = (const float*)d_in[5];
    const float* wf = (const float*)d_in[6];
    const float* bf = (const float*)d_in[7];
    const float* wr = (const float*)d_in[8];
    const float* br = (const float*)d_in[9];
    float* out = (float*)d_out;

    // Fused precompute (wproj0 + bias1 + detect), then (wproj1 + bias2)
    pre_kernel_A<<<515, 256>>>(wf, wr, bf, br, tgt32);
    pre_kernel_B<<<514, 256>>>(w2, b2);
    // Tensor-core GEMM1 (two-barrier, proven): g_h1 = relu(src @ w1 + b1)
    mma_gemm_relu<<<dim3(FEAT / BN, M_ROWS / BM), 256>>>(src, w1, b1);
    // Per-node 24-dim projections (lane=row, uniform weight loads, f32x2)
    rel_small_kernel<<<M_ROWS / 64, 256>>>();
    // edge logits + loss partials + tgt floats (fused)
    combine_loss_kernel<<<128, 256>>>(tgt32, out, out + OUT_LOGITS);
    // loss scalar -> d_out[819200]
    loss_final_kernel<<<1, 128>>>(out + OUT_LOGITS + N_EDGE);
}

// round 15
// speedup vs baseline: 1.1089x; 1.1089x over previous
#include <cuda_runtime.h>
#include <cuda_bf16.h>
#include <cstdint>

// Problem constants
#define M_ROWS   4096          // b*NT*2*NO = 16*8*32
#define K_VIS    2048
#define FEAT     512
#define BT       128           // b*NT
#define NO       16
#define TGT      24
#define N_EDGE   (BT * NO * NO)        // 32768
#define OUT_LOGITS (N_EDGE * TGT)      // 786432

typedef unsigned long long ull;

// Scratch (device globals; referenced ONLY in device code)
// NOTE: g_Ws/g_Wo/g_W2s/g_W2o are stored TRANSPOSED: [TGT][FEAT]
__device__ __align__(16) float g_h1[M_ROWS * FEAT];
__device__ __align__(16) float g_Ws[TGT * FEAT];     // (wf @ wr_top)^T
__device__ __align__(16) float g_Wo[TGT * FEAT];     // (wf @ wr_bot)^T
__device__ __align__(16) float g_W2s[TGT * FEAT];    // (w2 @ Ws)^T
__device__ __align__(16) float g_W2o[TGT * FEAT];    // (w2 @ Wo)^T
__device__ float g_bs[TGT];            // bf @ wr_top
__device__ float g_bo[TGT];            // bf @ wr_bot + br
__device__ float g_bs2[TGT];           // b2 @ Ws + bs
__device__ float g_bo2[TGT];           // b2 @ Wo + bo
__device__ __align__(16) float g_sout[BT * NO * TGT];
__device__ __align__(16) float g_oout[BT * NO * TGT];
__device__ float g_p1[128];
__device__ float g_p2[128];
__device__ int   g_tgt_is64;

// ---------------------------------------------------------------------------
// PTX helpers
// ---------------------------------------------------------------------------
__device__ __forceinline__ unsigned su32(const void* p) {
    return (unsigned)__cvta_generic_to_shared(p);
}
__device__ __forceinline__ unsigned packbf(float f0, float f1) {
    unsigned r;
    asm("cvt.rn.bf16x2.f32 %0, %1, %2;" : "=r"(r) : "f"(f1), "f"(f0));
    return r;
}
__device__ __forceinline__ void ldsm_x4(unsigned& r0, unsigned& r1,
                                        unsigned& r2, unsigned& r3,
                                        unsigned addr) {
    asm volatile("ldmatrix.sync.aligned.m8n8.x4.shared.b16 {%0,%1,%2,%3}, [%4];"
                 : "=r"(r0), "=r"(r1), "=r"(r2), "=r"(r3) : "r"(addr));
}
__device__ __forceinline__ void ldsm_x4t(unsigned& r0, unsigned& r1,
                                         unsigned& r2, unsigned& r3,
                                         unsigned addr) {
    asm volatile("ldmatrix.sync.aligned.m8n8.x4.trans.shared.b16 {%0,%1,%2,%3}, [%4];"
                 : "=r"(r0), "=r"(r1), "=r"(r2), "=r"(r3) : "r"(addr));
}
__device__ __forceinline__ void mma16816(float* c, const unsigned* a,
                                         const unsigned* b) {
    asm volatile(
        "mma.sync.aligned.m16n8k16.row.col.f32.bf16.bf16.f32 "
        "{%0,%1,%2,%3},{%4,%5,%6,%7},{%8,%9},{%0,%1,%2,%3};"
        : "+f"(c[0]), "+f"(c[1]), "+f"(c[2]), "+f"(c[3])
        : "r"(a[0]), "r"(a[1]), "r"(a[2]), "r"(a[3]), "r"(b[0]), "r"(b[1]));
}
__device__ __forceinline__ void split_store(float4 v, void* hp, void* lp) {
    unsigned h01 = packbf(v.x, v.y);
    unsigned h23 = packbf(v.z, v.w);
    float h0 = __uint_as_float(h01 << 16);
    float h1 = __uint_as_float(h01 & 0xffff0000u);
    float h2 = __uint_as_float(h23 << 16);
    float h3 = __uint_as_float(h23 & 0xffff0000u);
    unsigned l01 = packbf(v.x - h0, v.y - h1);
    unsigned l23 = packbf(v.z - h2, v.w - h3);
    *reinterpret_cast<uint2*>(hp) = make_uint2(h01, h23);
    *reinterpret_cast<uint2*>(lp) = make_uint2(l01, l23);
}
__device__ __forceinline__ void ffma2(ull& d, ull a, ull b) {
    asm("fma.rn.f32x2 %0, %1, %2, %0;" : "+l"(d) : "l"(a), "l"(b));
}
__device__ __forceinline__ void unpack2(float& lo, float& hi, ull v) {
    asm("mov.b64 {%0, %1}, %2;" : "=f"(lo), "=f"(hi) : "l"(v));
}

// ---------------------------------------------------------------------------
// GEMM1 via tensor cores (bf16 split, fp32-accurate) — proven, unchanged.
// g_h1 = relu(src @ w1 + b1),  M=4096, N=512, K=2048.
// ---------------------------------------------------------------------------
#define BM 128
#define BN 128
#define CK 32
#define APAD 40
#define BPAD 136

__global__ __launch_bounds__(256) void mma_gemm_relu(
    const float* __restrict__ A, const float* __restrict__ B,
    const float* __restrict__ bias)
{
    __shared__ __align__(16) __nv_bfloat16 sAh[BM][APAD];
    __shared__ __align__(16) __nv_bfloat16 sAl[BM][APAD];
    __shared__ __align__(16) __nv_bfloat16 sBh[CK][BPAD];
    __shared__ __align__(16) __nv_bfloat16 sBl[CK][BPAD];

    const int tid = threadIdx.x;
    const int lane = tid & 31;
    const int wid = tid >> 5;
    const int wm = wid & 1;
    const int wn = wid >> 1;
    const int bm = blockIdx.y * BM;
    const int bn = blockIdx.x * BN;

    const int arow = tid >> 3;
    const int acol = (tid & 7) * 4;
    const int brow = tid >> 5;
    const int bcol = (tid & 31) * 4;

    const float* Ap = A + (size_t)(bm + arow) * K_VIS + acol;
    const float* Bp = B + (size_t)brow * FEAT + bn + bcol;

    unsigned aAddrH[4], aAddrL[4];
#pragma unroll
    for (int mi = 0; mi < 4; mi++) {
        const int r = wm * 64 + mi * 16 + (lane & 15);
        const int c = (lane >> 4) * 8;
        aAddrH[mi] = su32(&sAh[r][c]);
        aAddrL[mi] = su32(&sAl[r][c]);
    }
    unsigned bAddrH[2], bAddrL[2];
#pragma unroll
    for (int nh = 0; nh < 2; nh++) {
        const int r = (lane & 15);
        const int c = wn * 32 + nh * 16 + (lane >> 4) * 8;
        bAddrH[nh] = su32(&sBh[r][c]);
        bAddrL[nh] = su32(&sBl[r][c]);
    }

    float acc[4][4][4];
#pragma unroll
    for (int mi = 0; mi < 4; mi++)
#pragma unroll
        for (int ni = 0; ni < 4; ni++)
#pragma unroll
            for (int q = 0; q < 4; q++) acc[mi][ni][q] = 0.0f;

    float4 aS[4], bS[4];
#pragma unroll
    for (int j = 0; j < 4; j++) {
        aS[j] = *reinterpret_cast<const float4*>(Ap + (size_t)j * 32 * K_VIS);
        bS[j] = *reinterpret_cast<const float4*>(Bp + (size_t)j * 8 * FEAT);
    }
#pragma unroll
    for (int j = 0; j < 4; j++) {
        split_store(aS[j], &sAh[arow + j * 32][acol], &sAl[arow + j * 32][acol]);
        split_store(bS[j], &sBh[brow + j * 8][bcol], &sBl[brow + j * 8][bcol]);
    }
    __syncthreads();

    const int nCh = K_VIS / CK;    // 64
    for (int ch = 0; ch < nCh; ch++) {
        const bool more = (ch + 1 < nCh);
        if (more) {
            const float* Ap2 = Ap + (ch + 1) * CK;
            const float* Bp2 = Bp + (size_t)(ch + 1) * CK * FEAT;
#pragma unroll
            for (int j = 0; j < 4; j++) {
                aS[j] = *reinterpret_cast<const float4*>(Ap2 + (size_t)j * 32 * K_VIS);
                bS[j] = *reinterpret_cast<const float4*>(Bp2 + (size_t)j * 8 * FEAT);
            }
        }

#pragma unroll
        for (int ks = 0; ks < 2; ks++) {
            const unsigned koff = ks * 16 * 2;
            unsigned ah[4][4], al[4][4], bh[2][4], bl[2][4];
#pragma unroll
            for (int mi = 0; mi < 4; mi++) {
                ldsm_x4(ah[mi][0], ah[mi][1], ah[mi][2], ah[mi][3],
                        aAddrH[mi] + koff);
                ldsm_x4(al[mi][0], al[mi][1], al[mi][2], al[mi][3],
                        aAddrL[mi] + koff);
            }
            const unsigned krow = ks * 16 * (BPAD * 2);
#pragma unroll
            for (int nh = 0; nh < 2; nh++) {
                ldsm_x4t(bh[nh][0], bh[nh][1], bh[nh][2], bh[nh][3],
                         bAddrH[nh] + krow);
                ldsm_x4t(bl[nh][0], bl[nh][1], bl[nh][2], bl[nh][3],
                         bAddrL[nh] + krow);
            }
#pragma unroll
            for (int mi = 0; mi < 4; mi++)
#pragma unroll
                for (int ni = 0; ni < 4; ni++) {
                    const int nh = ni >> 1;
                    const int sel = (ni & 1) * 2;
                    mma16816(acc[mi][ni], ah[mi], &bh[nh][sel]);
                    mma16816(acc[mi][ni], ah[mi], &bl[nh][sel]);
                    mma16816(acc[mi][ni], al[mi], &bh[nh][sel]);
                }
        }

        // Barrier 1: all warps done reading smem (ldsm) before overwrite
        __syncthreads();
        if (more) {
#pragma unroll
            for (int j = 0; j < 4; j++) {
                split_store(aS[j], &sAh[arow + j * 32][acol],
                            &sAl[arow + j * 32][acol]);
                split_store(bS[j], &sBh[brow + j * 8][bcol],
                            &sBl[brow + j * 8][bcol]);
            }
            // Barrier 2: stores visible before next chunk's ldsm
            __syncthreads();
        }
    }

#pragma unroll
    for (int ni = 0; ni < 4; ni++) {
        const int cn = bn + wn * 32 + ni * 8 + (lane & 3) * 2;
        const float2 bv = *reinterpret_cast<const float2*>(&bias[cn]);
#pragma unroll
        for (int mi = 0; mi < 4; mi++) {
            const int r0 = bm + wm * 64 + mi * 16 + (lane >> 2);
            float2 v0, v1;
            v0.x = fmaxf(acc[mi][ni][0] + bv.x, 0.0f);
            v0.y = fmaxf(acc[mi][ni][1] + bv.y, 0.0f);
            v1.x = fmaxf(acc[mi][ni][2] + bv.x, 0.0f);
            v1.y = fmaxf(acc[mi][ni][3] + bv.y, 0.0f);
            *reinterpret_cast<float2*>(&g_h1[(size_t)r0 * FEAT + cn]) = v0;
            *reinterpret_cast<float2*>(&g_h1[(size_t)(r0 + 8) * FEAT + cn]) = v1;
        }
    }
}

// ---------------------------------------------------------------------------
// proj4g (precompute kernels; unchanged from R13)
// ---------------------------------------------------------------------------
__device__ __forceinline__ void proj4g(
    const float* __restrict__ arow, const float* __restrict__ WT,
    int kc, int lane, float* acc)
{
    const int off = kc * 128 + lane * 4;
    const float4 v = *reinterpret_cast<const float4*>(arow + off);
#pragma unroll
    for (int t = 0; t < TGT; t++) {
        const float4 p =
            *reinterpret_cast<const float4*>(WT + (size_t)t * FEAT + off);
        float s = v.x * p.x;
        s = fmaf(v.y, p.y, s);
        s = fmaf(v.z, p.z, s);
        s = fmaf(v.w, p.w, s);
        acc[t] = s;
    }
#pragma unroll
    for (int t = 0; t < TGT; t++)
#pragma unroll
        for (int o = 16; o > 0; o >>= 1)
            acc[t] += __shfl_xor_sync(0xFFFFFFFFu, acc[t], o);
}

// ---------------------------------------------------------------------------
// Fused precompute A (unchanged from R13)
// ---------------------------------------------------------------------------
__global__ __launch_bounds__(256) void pre_kernel_A(
    const float* __restrict__ wf, const float* __restrict__ wr,
    const float* __restrict__ bf, const float* __restrict__ br,
    const int* __restrict__ tgt32)
{
    __shared__ float sbuf[TGT * FEAT];   // 48KB exactly; reused as sp later
    const int gx = blockIdx.x;
    const int w = threadIdx.x >> 5;
    const int lane = threadIdx.x & 31;

    if (gx < 512) {
        const int half = gx >> 8;
        const float* wrh = wr + (size_t)half * FEAT * TGT;
        for (int i4 = threadIdx.x; i4 < FEAT * TGT / 4; i4 += 256) {
            const float4 vv =
                *reinterpret_cast<const float4*>(wrh + (size_t)i4 * 4);
            const int e0 = i4 * 4;
            sbuf[(e0 % TGT) * FEAT + (e0 / TGT)] = vv.x;
            sbuf[((e0 + 1) % TGT) * FEAT + ((e0 + 1) / TGT)] = vv.y;
            sbuf[((e0 + 2) % TGT) * FEAT + ((e0 + 2) / TGT)] = vv.z;
            sbuf[((e0 + 3) % TGT) * FEAT + ((e0 + 3) / TGT)] = vv.w;
        }
        __syncthreads();

        const int f = (gx & 255) * 2 + (w >> 2);
        const int kc = w & 3;
        float acc[TGT];
        proj4g(wf + (size_t)f * FEAT, sbuf, kc, lane, acc);

        __syncthreads();
        if (lane < TGT) sbuf[w * TGT + lane] = acc[lane];
        __syncthreads();
        if ((w & 3) == 0 && lane < TGT) {
            const float s = sbuf[w * TGT + lane] + sbuf[(w + 1) * TGT + lane]
                          + sbuf[(w + 2) * TGT + lane]
                          + sbuf[(w + 3) * TGT + lane];
            float* dst = half ? g_Wo : g_Ws;
            dst[(size_t)lane * FEAT + f] = s;
        }
    } else if (gx < 514) {
        const int half = gx - 512;
#pragma unroll
        for (int rep = 0; rep < 3; rep++) {
            const int t = w + rep * 8;
            float s = 0.0f;
#pragma unroll
            for (int i = 0; i < 16; i++) {
                const int f = lane + 32 * i;
                s = fmaf(bf[f], wr[(size_t)(half * FEAT + f) * TGT + t], s);
            }
#pragma unroll
            for (int o = 16; o > 0; o >>= 1)
                s += __shfl_xor_sync(0xFFFFFFFFu, s, o);
            if (lane == 0) {
                if (half == 0) g_bs[t] = s;
                else           g_bo[t] = s + br[t];
            }
        }
    } else {
        if (threadIdx.x == 0) {
            int allzero = 1;
            for (int i = 1; i < 128; i += 2)
                if (tgt32[i] != 0) { allzero = 0; break; }
            g_tgt_is64 = allzero;
        }
    }
}

// ---------------------------------------------------------------------------
// Fused precompute B (unchanged from R13)
// ---------------------------------------------------------------------------
__global__ __launch_bounds__(256) void pre_kernel_B(
    const float* __restrict__ w2, const float* __restrict__ b2)
{
    __shared__ float sp[8 * TGT];
    const int gx = blockIdx.x;
    const int w = threadIdx.x >> 5;
    const int lane = threadIdx.x & 31;

    if (gx < 512) {
        const int half = gx >> 8;
        const float* P = half ? g_Wo : g_Ws;      // [TGT][FEAT]
        float* dst = half ? g_W2o : g_W2s;        // [TGT][FEAT]
        const int f = (gx & 255) * 2 + (w >> 2);
        const int kc = w & 3;

        float acc[TGT];
        proj4g(w2 + (size_t)f * FEAT, P, kc, lane, acc);

        if (lane < TGT) sp[w * TGT + lane] = acc[lane];
        __syncthreads();
        if ((w & 3) == 0 && lane < TGT) {
            const float s = sp[w * TGT + lane] + sp[(w + 1) * TGT + lane]
                          + sp[(w + 2) * TGT + lane]
                          + sp[(w + 3) * TGT + lane];
            dst[(size_t)lane * FEAT + f] = s;
        }
    } else if (gx < 514) {
        const int half = gx - 512;
        const float* W = half ? g_Wo : g_Ws;      // [TGT][FEAT]
#pragma unroll
        for (int rep = 0; rep < 3; rep++) {
            const int t = w + rep * 8;
            float s = 0.0f;
#pragma unroll
            for (int i = 0; i < 16; i++) {
                const int f = lane + 32 * i;
                s = fmaf(b2[f], W[(size_t)t * FEAT + f], s);
            }
#pragma unroll
            for (int o = 16; o > 0; o >>= 1)
                s += __shfl_xor_sync(0xFFFFFFFFu, s, o);
            if (lane == 0) {
                if (half == 0) g_bs2[t] = s + g_bs[t];
                else           g_bo2[t] = s + g_bo[t];
            }
        }
    }
}

// ---------------------------------------------------------------------------
// Rel projection v4: 128 blocks x 256 threads.
// Block = one (frame-pair, type) group: 32 same-type rows from 2 frames.
// Warp w = k-chunk of 64 (8 chunks cover K=512); lane = row.
// Weight loads warp-uniform; f32x2 accumulators; 8-way partial combine.
// ---------------------------------------------------------------------------
__global__ __launch_bounds__(256) void rel_small_kernel()
{
    __shared__ float sh[8][32][TGT];   // 24 KB partials
    const int w = threadIdx.x >> 5;        // k-chunk 0..7
    const int lane = threadIdx.x & 31;
    const int type = blockIdx.x & 1;       // 0 = subject, 1 = object
    const int fp = blockIdx.x >> 1;        // frame pair 0..63
    const int frame = lane >> 4;           // 0..1
    const int n = lane & 15;
    const int row = fp * 64 + frame * 32 + type * NO + n;

    const float* __restrict__ WT = type ? g_W2o : g_W2s;   // [TGT][FEAT]
    const float* __restrict__ hrow = g_h1 + (size_t)row * FEAT + w * 64;
    const float* __restrict__ wbase = WT + w * 64;

    ull accp[TGT];
#pragma unroll
    for (int t = 0; t < TGT; t++) accp[t] = 0ull;

#pragma unroll 4
    for (int kg = 0; kg < 16; kg++) {
        const float4 v4 = *reinterpret_cast<const float4*>(hrow + kg * 4);
        const ull v01 = reinterpret_cast<const ull*>(&v4)[0];
        const ull v23 = reinterpret_cast<const ull*>(&v4)[1];
#pragma unroll
        for (int t = 0; t < TGT; t++) {
            const float4 w4 = __ldg(reinterpret_cast<const float4*>(
                wbase + (size_t)t * FEAT + kg * 4));
            const ull w01 = reinterpret_cast<const ull*>(&w4)[0];
            const ull w23 = reinterpret_cast<const ull*>(&w4)[1];
            ffma2(accp[t], v01, w01);
            ffma2(accp[t], v23, w23);
        }
    }

#pragma unroll
    for (int t = 0; t < TGT; t++) {
        float lo, hi;
        unpack2(lo, hi, accp[t]);
        sh[w][lane][t] = lo + hi;
    }
    __syncthreads();

    // Epilogue: 32 rows x 24 t = 768 outputs, 3 per thread
#pragma unroll
    for (int q = 0; q < 3; q++) {
        const int idx = threadIdx.x * 3 + q;
        const int rl = idx / TGT;          // 0..31 local row
        const int t = idx - rl * TGT;
        float v = sh[0][rl][t] + sh[1][rl][t] + sh[2][rl][t] + sh[3][rl][t]
                + sh[4][rl][t] + sh[5][rl][t] + sh[6][rl][t] + sh[7][rl][t];
        v += type ? g_bo2[t] : g_bs2[t];
        const int fr = rl >> 4;
        const int nn = rl & 15;
        const int bt = fp * 2 + fr;
        float* dst = type ? g_oout : g_sout;
        dst[(size_t)(bt * NO + nn) * TGT + t] = v;
    }
}

// ---------------------------------------------------------------------------
// Fused edge combine + weighted-NLL partials (unchanged).
// ---------------------------------------------------------------------------
__global__ __launch_bounds__(256) void combine_loss_kernel(
    const int* __restrict__ tgt32, float* __restrict__ out,
    float* __restrict__ tgtf)
{
    __shared__ float ss[NO * TGT];
    __shared__ float so[NO * TGT];
    __shared__ float sh1[256], sh2[256];

    const int bt = blockIdx.x;
    if (threadIdx.x < 96) {
        const int o = threadIdx.x * 4;
        *reinterpret_cast<float4*>(&ss[o]) =
            *reinterpret_cast<const float4*>(&g_sout[(size_t)bt * NO * TGT + o]);
        *reinterpret_cast<float4*>(&so[o]) =
            *reinterpret_cast<const float4*>(&g_oout[(size_t)bt * NO * TGT + o]);
    }
    __syncthreads();

    const int e = threadIdx.x;
    const int i = e >> 4;
    const int j = e & 15;
    const int r = bt * 256 + e;

    float lg[TGT];
#pragma unroll
    for (int t = 0; t < TGT; t++) lg[t] = ss[i * TGT + t] + so[j * TGT + t];

    float* op = out + (size_t)r * TGT;
#pragma unroll
    for (int q = 0; q < 6; q++)
        *reinterpret_cast<float4*>(op + q * 4) =
            make_float4(lg[q * 4], lg[q * 4 + 1], lg[q * 4 + 2], lg[q * 4 + 3]);

    float m = lg[0];
#pragma unroll
    for (int t = 1; t < TGT; t++) m = fmaxf(m, lg[t]);
    float s = 0.0f;
#pragma unroll
    for (int t = 0; t < TGT; t++) s += expf(lg[t] - m);
    const int tg = g_tgt_is64 ? tgt32[2 * r] : tgt32[r];
    const float nll = logf(s) + m - lg[tg];
    const float wgt = (tg == 0) ? 1.0f : 100.0f;
    tgtf[r] = (float)tg;

    sh1[e] = wgt * nll;
    sh2[e] = wgt;
    __syncthreads();
    for (int off = 128; off > 0; off >>= 1) {
        if (e < off) {
            sh1[e] += sh1[e + off];
            sh2[e] += sh2[e + off];
        }
        __syncthreads();
    }
    if (e == 0) { g_p1[bt] = sh1[0]; g_p2[bt] = sh2[0]; }
}

__global__ __launch_bounds__(128) void loss_final_kernel(float* __restrict__ loss)
{
    __shared__ float sh1[128], sh2[128];
    sh1[threadIdx.x] = g_p1[threadIdx.x];
    sh2[threadIdx.x] = g_p2[threadIdx.x];
    __syncthreads();
    for (int off = 64; off > 0; off >>= 1) {
        if (threadIdx.x < off) {
            sh1[threadIdx.x] += sh1[threadIdx.x + off];
            sh2[threadIdx.x] += sh2[threadIdx.x + off];
        }
        __syncthreads();
    }
    if (threadIdx.x == 0) loss[0] = sh1[0] / sh2[0];
}

// ---------------------------------------------------------------------------
extern "C" void kernel_launch(void* const* d_in, const int* in_sizes, int n_in,
                              void* d_out, int out_size)
{
    const float* src   = (const float*)d_in[0];
    const int*   tgt32 = (const int*)d_in[1];
    const float* w1 = (const float*)d_in[2];
    const float* b1 = (const float*)d_in[3];
    const float* w2 = (const float*)d_in[4];
    const float* b2 = (const float*)d_in[5];
    const float* wf = (const float*)d_in[6];
    const float* bf = (const float*)d_in[7];
    const float* wr = (const float*)d_in[8];
    const float* br = (const float*)d_in[9];
    float* out = (float*)d_out;

    // Fused precompute (wproj0 + bias1 + detect), then (wproj1 + bias2)
    pre_kernel_A<<<515, 256>>>(wf, wr, bf, br, tgt32);
    pre_kernel_B<<<514, 256>>>(w2, b2);
    // Tensor-core GEMM1 (two-barrier, proven): g_h1 = relu(src @ w1 + b1)
    mma_gemm_relu<<<dim3(FEAT / BN, M_ROWS / BM), 256>>>(src, w1, b1);
    // Per-node 24-dim projections (1 block per 32-row type-group, K split 8)
    rel_small_kernel<<<128, 256>>>();
    // edge logits + loss partials + tgt floats (fused)
    combine_loss_kernel<<<128, 256>>>(tgt32, out, out + OUT_LOGITS);
    // loss scalar -> d_out[819200]
    loss_final_kernel<<<1, 128>>>(out + OUT_LOGITS + N_EDGE);
}

// round 16
// speedup vs baseline: 1.1658x; 1.0513x over previous
#include <cuda_runtime.h>
#include <cuda_bf16.h>
#include <cstdint>

// Problem constants
#define M_ROWS   4096          // b*NT*2*NO = 16*8*32
#define K_VIS    2048
#define FEAT     512
#define BT       128           // b*NT
#define NO       16
#define TGT      24
#define N_EDGE   (BT * NO * NO)        // 32768
#define OUT_LOGITS (N_EDGE * TGT)      // 786432

typedef unsigned long long ull;

// Scratch (device globals; referenced ONLY in device code)
// NOTE: g_Ws/g_Wo/g_W2s/g_W2o are stored TRANSPOSED: [TGT][FEAT]
__device__ __align__(16) float g_h1[M_ROWS * FEAT];
__device__ __align__(16) float g_Ws[TGT * FEAT];     // (wf @ wr_top)^T
__device__ __align__(16) float g_Wo[TGT * FEAT];     // (wf @ wr_bot)^T
__device__ __align__(16) float g_W2s[TGT * FEAT];    // (w2 @ Ws)^T
__device__ __align__(16) float g_W2o[TGT * FEAT];    // (w2 @ Wo)^T
__device__ float g_bs[TGT];            // bf @ wr_top
__device__ float g_bo[TGT];            // bf @ wr_bot + br
__device__ float g_bs2[TGT];           // b2 @ Ws + bs
__device__ float g_bo2[TGT];           // b2 @ Wo + bo
__device__ __align__(16) float g_sout[BT * NO * TGT];
__device__ __align__(16) float g_oout[BT * NO * TGT];
__device__ float g_p1[128];
__device__ float g_p2[128];
__device__ int   g_tgt_is64;

// ---------------------------------------------------------------------------
// PTX helpers
// ---------------------------------------------------------------------------
__device__ __forceinline__ unsigned su32(const void* p) {
    return (unsigned)__cvta_generic_to_shared(p);
}
__device__ __forceinline__ unsigned packbf(float f0, float f1) {
    unsigned r;
    asm("cvt.rn.bf16x2.f32 %0, %1, %2;" : "=r"(r) : "f"(f1), "f"(f0));
    return r;
}
__device__ __forceinline__ void ldsm_x4(unsigned& r0, unsigned& r1,
                                        unsigned& r2, unsigned& r3,
                                        unsigned addr) {
    asm volatile("ldmatrix.sync.aligned.m8n8.x4.shared.b16 {%0,%1,%2,%3}, [%4];"
                 : "=r"(r0), "=r"(r1), "=r"(r2), "=r"(r3) : "r"(addr));
}
__device__ __forceinline__ void ldsm_x4t(unsigned& r0, unsigned& r1,
                                         unsigned& r2, unsigned& r3,
                                         unsigned addr) {
    asm volatile("ldmatrix.sync.aligned.m8n8.x4.trans.shared.b16 {%0,%1,%2,%3}, [%4];"
                 : "=r"(r0), "=r"(r1), "=r"(r2), "=r"(r3) : "r"(addr));
}
__device__ __forceinline__ void mma16816(float* c, const unsigned* a,
                                         const unsigned* b) {
    asm volatile(
        "mma.sync.aligned.m16n8k16.row.col.f32.bf16.bf16.f32 "
        "{%0,%1,%2,%3},{%4,%5,%6,%7},{%8,%9},{%0,%1,%2,%3};"
        : "+f"(c[0]), "+f"(c[1]), "+f"(c[2]), "+f"(c[3])
        : "r"(a[0]), "r"(a[1]), "r"(a[2]), "r"(a[3]), "r"(b[0]), "r"(b[1]));
}
__device__ __forceinline__ void split_store(float4 v, void* hp, void* lp) {
    unsigned h01 = packbf(v.x, v.y);
    unsigned h23 = packbf(v.z, v.w);
    float h0 = __uint_as_float(h01 << 16);
    float h1 = __uint_as_float(h01 & 0xffff0000u);
    float h2 = __uint_as_float(h23 << 16);
    float h3 = __uint_as_float(h23 & 0xffff0000u);
    unsigned l01 = packbf(v.x - h0, v.y - h1);
    unsigned l23 = packbf(v.z - h2, v.w - h3);
    *reinterpret_cast<uint2*>(hp) = make_uint2(h01, h23);
    *reinterpret_cast<uint2*>(lp) = make_uint2(l01, l23);
}
__device__ __forceinline__ void ffma2(ull& d, ull a, ull b) {
    asm("fma.rn.f32x2 %0, %1, %2, %0;" : "+l"(d) : "l"(a), "l"(b));
}
__device__ __forceinline__ void unpack2(float& lo, float& hi, ull v) {
    asm("mov.b64 {%0, %1}, %2;" : "=f"(lo), "=f"(hi) : "l"(v));
}

// ---------------------------------------------------------------------------
// GEMM1 via tensor cores (bf16 split, fp32-accurate) — proven, unchanged.
// g_h1 = relu(src @ w1 + b1),  M=4096, N=512, K=2048.
// ---------------------------------------------------------------------------
#define BM 128
#define BN 128
#define CK 32
#define APAD 40
#define BPAD 136

__global__ __launch_bounds__(256) void mma_gemm_relu(
    const float* __restrict__ A, const float* __restrict__ B,
    const float* __restrict__ bias)
{
    __shared__ __align__(16) __nv_bfloat16 sAh[BM][APAD];
    __shared__ __align__(16) __nv_bfloat16 sAl[BM][APAD];
    __shared__ __align__(16) __nv_bfloat16 sBh[CK][BPAD];
    __shared__ __align__(16) __nv_bfloat16 sBl[CK][BPAD];

    const int tid = threadIdx.x;
    const int lane = tid & 31;
    const int wid = tid >> 5;
    const int wm = wid & 1;
    const int wn = wid >> 1;
    const int bm = blockIdx.y * BM;
    const int bn = blockIdx.x * BN;

    const int arow = tid >> 3;
    const int acol = (tid & 7) * 4;
    const int brow = tid >> 5;
    const int bcol = (tid & 31) * 4;

    const float* Ap = A + (size_t)(bm + arow) * K_VIS + acol;
    const float* Bp = B + (size_t)brow * FEAT + bn + bcol;

    unsigned aAddrH[4], aAddrL[4];
#pragma unroll
    for (int mi = 0; mi < 4; mi++) {
        const int r = wm * 64 + mi * 16 + (lane & 15);
        const int c = (lane >> 4) * 8;
        aAddrH[mi] = su32(&sAh[r][c]);
        aAddrL[mi] = su32(&sAl[r][c]);
    }
    unsigned bAddrH[2], bAddrL[2];
#pragma unroll
    for (int nh = 0; nh < 2; nh++) {
        const int r = (lane & 15);
        const int c = wn * 32 + nh * 16 + (lane >> 4) * 8;
        bAddrH[nh] = su32(&sBh[r][c]);
        bAddrL[nh] = su32(&sBl[r][c]);
    }

    float acc[4][4][4];
#pragma unroll
    for (int mi = 0; mi < 4; mi++)
#pragma unroll
        for (int ni = 0; ni < 4; ni++)
#pragma unroll
            for (int q = 0; q < 4; q++) acc[mi][ni][q] = 0.0f;

    float4 aS[4], bS[4];
#pragma unroll
    for (int j = 0; j < 4; j++) {
        aS[j] = *reinterpret_cast<const float4*>(Ap + (size_t)j * 32 * K_VIS);
        bS[j] = *reinterpret_cast<const float4*>(Bp + (size_t)j * 8 * FEAT);
    }
#pragma unroll
    for (int j = 0; j < 4; j++) {
        split_store(aS[j], &sAh[arow + j * 32][acol], &sAl[arow + j * 32][acol]);
        split_store(bS[j], &sBh[brow + j * 8][bcol], &sBl[brow + j * 8][bcol]);
    }
    __syncthreads();

    const int nCh = K_VIS / CK;    // 64
    for (int ch = 0; ch < nCh; ch++) {
        const bool more = (ch + 1 < nCh);
        if (more) {
            const float* Ap2 = Ap + (ch + 1) * CK;
            const float* Bp2 = Bp + (size_t)(ch + 1) * CK * FEAT;
#pragma unroll
            for (int j = 0; j < 4; j++) {
                aS[j] = *reinterpret_cast<const float4*>(Ap2 + (size_t)j * 32 * K_VIS);
                bS[j] = *reinterpret_cast<const float4*>(Bp2 + (size_t)j * 8 * FEAT);
            }
        }

#pragma unroll
        for (int ks = 0; ks < 2; ks++) {
            const unsigned koff = ks * 16 * 2;
            unsigned ah[4][4], al[4][4], bh[2][4], bl[2][4];
#pragma unroll
            for (int mi = 0; mi < 4; mi++) {
                ldsm_x4(ah[mi][0], ah[mi][1], ah[mi][2], ah[mi][3],
                        aAddrH[mi] + koff);
                ldsm_x4(al[mi][0], al[mi][1], al[mi][2], al[mi][3],
                        aAddrL[mi] + koff);
            }
            const unsigned krow = ks * 16 * (BPAD * 2);
#pragma unroll
            for (int nh = 0; nh < 2; nh++) {
                ldsm_x4t(bh[nh][0], bh[nh][1], bh[nh][2], bh[nh][3],
                         bAddrH[nh] + krow);
                ldsm_x4t(bl[nh][0], bl[nh][1], bl[nh][2], bl[nh][3],
                         bAddrL[nh] + krow);
            }
#pragma unroll
            for (int mi = 0; mi < 4; mi++)
#pragma unroll
                for (int ni = 0; ni < 4; ni++) {
                    const int nh = ni >> 1;
                    const int sel = (ni & 1) * 2;
                    mma16816(acc[mi][ni], ah[mi], &bh[nh][sel]);
                    mma16816(acc[mi][ni], ah[mi], &bl[nh][sel]);
                    mma16816(acc[mi][ni], al[mi], &bh[nh][sel]);
                }
        }

        // Barrier 1: all warps done reading smem (ldsm) before overwrite
        __syncthreads();
        if (more) {
#pragma unroll
            for (int j = 0; j < 4; j++) {
                split_store(aS[j], &sAh[arow + j * 32][acol],
                            &sAl[arow + j * 32][acol]);
                split_store(bS[j], &sBh[brow + j * 8][bcol],
                            &sBl[brow + j * 8][bcol]);
            }
            // Barrier 2: stores visible before next chunk's ldsm
            __syncthreads();
        }
    }

#pragma unroll
    for (int ni = 0; ni < 4; ni++) {
        const int cn = bn + wn * 32 + ni * 8 + (lane & 3) * 2;
        const float2 bv = *reinterpret_cast<const float2*>(&bias[cn]);
#pragma unroll
        for (int mi = 0; mi < 4; mi++) {
            const int r0 = bm + wm * 64 + mi * 16 + (lane >> 2);
            float2 v0, v1;
            v0.x = fmaxf(acc[mi][ni][0] + bv.x, 0.0f);
            v0.y = fmaxf(acc[mi][ni][1] + bv.y, 0.0f);
            v1.x = fmaxf(acc[mi][ni][2] + bv.x, 0.0f);
            v1.y = fmaxf(acc[mi][ni][3] + bv.y, 0.0f);
            *reinterpret_cast<float2*>(&g_h1[(size_t)r0 * FEAT + cn]) = v0;
            *reinterpret_cast<float2*>(&g_h1[(size_t)(r0 + 8) * FEAT + cn]) = v1;
        }
    }
}

// ---------------------------------------------------------------------------
// proj4g (precompute kernels; unchanged)
// ---------------------------------------------------------------------------
__device__ __forceinline__ void proj4g(
    const float* __restrict__ arow, const float* __restrict__ WT,
    int kc, int lane, float* acc)
{
    const int off = kc * 128 + lane * 4;
    const float4 v = *reinterpret_cast<const float4*>(arow + off);
#pragma unroll
    for (int t = 0; t < TGT; t++) {
        const float4 p =
            *reinterpret_cast<const float4*>(WT + (size_t)t * FEAT + off);
        float s = v.x * p.x;
        s = fmaf(v.y, p.y, s);
        s = fmaf(v.z, p.z, s);
        s = fmaf(v.w, p.w, s);
        acc[t] = s;
    }
#pragma unroll
    for (int t = 0; t < TGT; t++)
#pragma unroll
        for (int o = 16; o > 0; o >>= 1)
            acc[t] += __shfl_xor_sync(0xFFFFFFFFu, acc[t], o);
}

// ---------------------------------------------------------------------------
// Fused precompute A (unchanged)
// ---------------------------------------------------------------------------
__global__ __launch_bounds__(256) void pre_kernel_A(
    const float* __restrict__ wf, const float* __restrict__ wr,
    const float* __restrict__ bf, const float* __restrict__ br,
    const int* __restrict__ tgt32)
{
    __shared__ float sbuf[TGT * FEAT];   // 48KB exactly; reused as sp later
    const int gx = blockIdx.x;
    const int w = threadIdx.x >> 5;
    const int lane = threadIdx.x & 31;

    if (gx < 512) {
        const int half = gx >> 8;
        const float* wrh = wr + (size_t)half * FEAT * TGT;
        for (int i4 = threadIdx.x; i4 < FEAT * TGT / 4; i4 += 256) {
            const float4 vv =
                *reinterpret_cast<const float4*>(wrh + (size_t)i4 * 4);
            const int e0 = i4 * 4;
            sbuf[(e0 % TGT) * FEAT + (e0 / TGT)] = vv.x;
            sbuf[((e0 + 1) % TGT) * FEAT + ((e0 + 1) / TGT)] = vv.y;
            sbuf[((e0 + 2) % TGT) * FEAT + ((e0 + 2) / TGT)] = vv.z;
            sbuf[((e0 + 3) % TGT) * FEAT + ((e0 + 3) / TGT)] = vv.w;
        }
        __syncthreads();

        const int f = (gx & 255) * 2 + (w >> 2);
        const int kc = w & 3;
        float acc[TGT];
        proj4g(wf + (size_t)f * FEAT, sbuf, kc, lane, acc);

        __syncthreads();
        if (lane < TGT) sbuf[w * TGT + lane] = acc[lane];
        __syncthreads();
        if ((w & 3) == 0 && lane < TGT) {
            const float s = sbuf[w * TGT + lane] + sbuf[(w + 1) * TGT + lane]
                          + sbuf[(w + 2) * TGT + lane]
                          + sbuf[(w + 3) * TGT + lane];
            float* dst = half ? g_Wo : g_Ws;
            dst[(size_t)lane * FEAT + f] = s;
        }
    } else if (gx < 514) {
        const int half = gx - 512;
#pragma unroll
        for (int rep = 0; rep < 3; rep++) {
            const int t = w + rep * 8;
            float s = 0.0f;
#pragma unroll
            for (int i = 0; i < 16; i++) {
                const int f = lane + 32 * i;
                s = fmaf(bf[f], wr[(size_t)(half * FEAT + f) * TGT + t], s);
            }
#pragma unroll
            for (int o = 16; o > 0; o >>= 1)
                s += __shfl_xor_sync(0xFFFFFFFFu, s, o);
            if (lane == 0) {
                if (half == 0) g_bs[t] = s;
                else           g_bo[t] = s + br[t];
            }
        }
    } else {
        if (threadIdx.x == 0) {
            int allzero = 1;
            for (int i = 1; i < 128; i += 2)
                if (tgt32[i] != 0) { allzero = 0; break; }
            g_tgt_is64 = allzero;
        }
    }
}

// ---------------------------------------------------------------------------
// Fused precompute B (unchanged)
// ---------------------------------------------------------------------------
__global__ __launch_bounds__(256) void pre_kernel_B(
    const float* __restrict__ w2, const float* __restrict__ b2)
{
    __shared__ float sp[8 * TGT];
    const int gx = blockIdx.x;
    const int w = threadIdx.x >> 5;
    const int lane = threadIdx.x & 31;

    if (gx < 512) {
        const int half = gx >> 8;
        const float* P = half ? g_Wo : g_Ws;      // [TGT][FEAT]
        float* dst = half ? g_W2o : g_W2s;        // [TGT][FEAT]
        const int f = (gx & 255) * 2 + (w >> 2);
        const int kc = w & 3;

        float acc[TGT];
        proj4g(w2 + (size_t)f * FEAT, P, kc, lane, acc);

        if (lane < TGT) sp[w * TGT + lane] = acc[lane];
        __syncthreads();
        if ((w & 3) == 0 && lane < TGT) {
            const float s = sp[w * TGT + lane] + sp[(w + 1) * TGT + lane]
                          + sp[(w + 2) * TGT + lane]
                          + sp[(w + 3) * TGT + lane];
            dst[(size_t)lane * FEAT + f] = s;
        }
    } else if (gx < 514) {
        const int half = gx - 512;
        const float* W = half ? g_Wo : g_Ws;      // [TGT][FEAT]
#pragma unroll
        for (int rep = 0; rep < 3; rep++) {
            const int t = w + rep * 8;
            float s = 0.0f;
#pragma unroll
            for (int i = 0; i < 16; i++) {
                const int f = lane + 32 * i;
                s = fmaf(b2[f], W[(size_t)t * FEAT + f], s);
            }
#pragma unroll
            for (int o = 16; o > 0; o >>= 1)
                s += __shfl_xor_sync(0xFFFFFFFFu, s, o);
            if (lane == 0) {
                if (half == 0) g_bs2[t] = s + g_bs[t];
                else           g_bo2[t] = s + g_bo[t];
            }
        }
    }
}

// ---------------------------------------------------------------------------
// Rel projection v5: 128 blocks x 512 threads (16 warps).
// Block = one (frame-pair, type) group: 32 same-type rows from 2 frames.
// Warp w = k-chunk of 32 (16 chunks cover K=512); lane = row.
// Weight loads warp-uniform; f32x2 accumulators; 16-way partial combine.
// ---------------------------------------------------------------------------
__global__ __launch_bounds__(512) void rel_small_kernel()
{
    __shared__ float sh[16][32][TGT];  // 48 KB partials
    const int w = threadIdx.x >> 5;        // k-chunk 0..15
    const int lane = threadIdx.x & 31;
    const int type = blockIdx.x & 1;       // 0 = subject, 1 = object
    const int fp = blockIdx.x >> 1;        // frame pair 0..63
    const int frame = lane >> 4;           // 0..1
    const int n = lane & 15;
    const int row = fp * 64 + frame * 32 + type * NO + n;

    const float* __restrict__ WT = type ? g_W2o : g_W2s;   // [TGT][FEAT]
    const float* __restrict__ hrow = g_h1 + (size_t)row * FEAT + w * 32;
    const float* __restrict__ wbase = WT + w * 32;

    ull accp[TGT];
#pragma unroll
    for (int t = 0; t < TGT; t++) accp[t] = 0ull;

#pragma unroll
    for (int kg = 0; kg < 8; kg++) {
        const float4 v4 = *reinterpret_cast<const float4*>(hrow + kg * 4);
        const ull v01 = reinterpret_cast<const ull*>(&v4)[0];
        const ull v23 = reinterpret_cast<const ull*>(&v4)[1];
#pragma unroll
        for (int t = 0; t < TGT; t++) {
            const float4 w4 = __ldg(reinterpret_cast<const float4*>(
                wbase + (size_t)t * FEAT + kg * 4));
            const ull w01 = reinterpret_cast<const ull*>(&w4)[0];
            const ull w23 = reinterpret_cast<const ull*>(&w4)[1];
            ffma2(accp[t], v01, w01);
            ffma2(accp[t], v23, w23);
        }
    }

#pragma unroll
    for (int t = 0; t < TGT; t++) {
        float lo, hi;
        unpack2(lo, hi, accp[t]);
        sh[w][lane][t] = lo + hi;
    }
    __syncthreads();

    // Epilogue: 32 rows x 24 t = 768 outputs over 512 threads
    for (int idx = threadIdx.x; idx < 32 * TGT; idx += 512) {
        const int rl = idx / TGT;          // 0..31 local row
        const int t = idx - rl * TGT;
        float v = 0.0f;
#pragma unroll
        for (int ww = 0; ww < 16; ww++) v += sh[ww][rl][t];
        v += type ? g_bo2[t] : g_bs2[t];
        const int fr = rl >> 4;
        const int nn = rl & 15;
        const int bt = fp * 2 + fr;
        float* dst = type ? g_oout : g_sout;
        dst[(size_t)(bt * NO + nn) * TGT + t] = v;
    }
}

// ---------------------------------------------------------------------------
// Fused edge combine + weighted-NLL partials (unchanged).
// ---------------------------------------------------------------------------
__global__ __launch_bounds__(256) void combine_loss_kernel(
    const int* __restrict__ tgt32, float* __restrict__ out,
    float* __restrict__ tgtf)
{
    __shared__ float ss[NO * TGT];
    __shared__ float so[NO * TGT];
    __shared__ float sh1[256], sh2[256];

    const int bt = blockIdx.x;
    if (threadIdx.x < 96) {
        const int o = threadIdx.x * 4;
        *reinterpret_cast<float4*>(&ss[o]) =
            *reinterpret_cast<const float4*>(&g_sout[(size_t)bt * NO * TGT + o]);
        *reinterpret_cast<float4*>(&so[o]) =
            *reinterpret_cast<const float4*>(&g_oout[(size_t)bt * NO * TGT + o]);
    }
    __syncthreads();

    const int e = threadIdx.x;
    const int i = e >> 4;
    const int j = e & 15;
    const int r = bt * 256 + e;

    float lg[TGT];
#pragma unroll
    for (int t = 0; t < TGT; t++) lg[t] = ss[i * TGT + t] + so[j * TGT + t];

    float* op = out + (size_t)r * TGT;
#pragma unroll
    for (int q = 0; q < 6; q++)
        *reinterpret_cast<float4*>(op + q * 4) =
            make_float4(lg[q * 4], lg[q * 4 + 1], lg[q * 4 + 2], lg[q * 4 + 3]);

    float m = lg[0];
#pragma unroll
    for (int t = 1; t < TGT; t++) m = fmaxf(m, lg[t]);
    float s = 0.0f;
#pragma unroll
    for (int t = 0; t < TGT; t++) s += expf(lg[t] - m);
    const int tg = g_tgt_is64 ? tgt32[2 * r] : tgt32[r];
    const float nll = logf(s) + m - lg[tg];
    const float wgt = (tg == 0) ? 1.0f : 100.0f;
    tgtf[r] = (float)tg;

    sh1[e] = wgt * nll;
    sh2[e] = wgt;
    __syncthreads();
    for (int off = 128; off > 0; off >>= 1) {
        if (e < off) {
            sh1[e] += sh1[e + off];
            sh2[e] += sh2[e + off];
        }
        __syncthreads();
    }
    if (e == 0) { g_p1[bt] = sh1[0]; g_p2[bt] = sh2[0]; }
}

__global__ __launch_bounds__(128) void loss_final_kernel(float* __restrict__ loss)
{
    __shared__ float sh1[128], sh2[128];
    sh1[threadIdx.x] = g_p1[threadIdx.x];
    sh2[threadIdx.x] = g_p2[threadIdx.x];
    __syncthreads();
    for (int off = 64; off > 0; off >>= 1) {
        if (threadIdx.x < off) {
            sh1[threadIdx.x] += sh1[threadIdx.x + off];
            sh2[threadIdx.x] += sh2[threadIdx.x + off];
        }
        __syncthreads();
    }
    if (threadIdx.x == 0) loss[0] = sh1[0] / sh2[0];
}

// ---------------------------------------------------------------------------
extern "C" void kernel_launch(void* const* d_in, const int* in_sizes, int n_in,
                              void* d_out, int out_size)
{
    const float* src   = (const float*)d_in[0];
    const int*   tgt32 = (const int*)d_in[1];
    const float* w1 = (const float*)d_in[2];
    const float* b1 = (const float*)d_in[3];
    const float* w2 = (const float*)d_in[4];
    const float* b2 = (const float*)d_in[5];
    const float* wf = (const float*)d_in[6];
    const float* bf = (const float*)d_in[7];
    const float* wr = (const float*)d_in[8];
    const float* br = (const float*)d_in[9];
    float* out = (float*)d_out;

    // Fused precompute (wproj0 + bias1 + detect), then (wproj1 + bias2)
    pre_kernel_A<<<515, 256>>>(wf, wr, bf, br, tgt32);
    pre_kernel_B<<<514, 256>>>(w2, b2);
    // Tensor-core GEMM1 (two-barrier, proven): g_h1 = relu(src @ w1 + b1)
    mma_gemm_relu<<<dim3(FEAT / BN, M_ROWS / BM), 256>>>(src, w1, b1);
    // Per-node 24-dim projections (32-row type-groups, K split 16 ways)
    rel_small_kernel<<<128, 512>>>();
    // edge logits + loss partials + tgt floats (fused)
    combine_loss_kernel<<<128, 256>>>(tgt32, out, out + OUT_LOGITS);
    // loss scalar -> d_out[819200]
    loss_final_kernel<<<1, 128>>>(out + OUT_LOGITS + N_EDGE);
}